// round 4
// baseline (speedup 1.0000x reference)
#include <cuda_runtime.h>
#include <cstdint>

#define NN 50000
#define EE 800000
#define DD 128

// ---------------- scratch (static device globals; no allocation allowed) ----
__device__ __align__(16) float g_q[NN * DD];
__device__ __align__(16) float g_k[NN * DD];
__device__ __align__(16) float g_v[NN * DD];
__device__ __align__(16) float g_skip[NN * DD];
__device__ __align__(16) float g_h[NN * DD];

__device__ __align__(16) int g_deg[NN];
__device__ __align__(16) int g_off[NN + 2];
__device__ __align__(16) int g_cursor[NN];
__device__ __align__(16) int g_bsum[128];
__device__ __align__(16) int g_boff[128];
__device__ __align__(16) int g_csrc[EE];
__device__ int g_is64;

// ---------------- edge_index dtype detection --------------------------------
// If the buffer is int64, words at odd int32 positions (hi words of values
// < 2^32) are all zero. If int32, those positions hold random node ids in
// [0, 50000) — nonzero with prob 1-1/50000 each; 1024 samples decide.
__global__ void k_detect(const int* __restrict__ p) {
    __shared__ int any;
    if (threadIdx.x == 0) any = 0;
    __syncthreads();
    int nz = 0;
    for (int i = threadIdx.x; i < 1024; i += 256) nz |= p[2 * i + 1];
    if (nz) any = 1;
    __syncthreads();
    if (threadIdx.x == 0) g_is64 = (any == 0);
}

__device__ __forceinline__ int load_edge(const void* ei, long long idx) {
    int v;
    if (g_is64) v = (int)((const long long*)ei)[idx];
    else        v = ((const int*)ei)[idx];
    // clamp: no stray atomic/gather can trap even if data is adversarial
    return min(max(v, 0), NN - 1);
}

// ---------------- CSR build -------------------------------------------------
__global__ void k_zero_deg() {
    int i = blockIdx.x * blockDim.x + threadIdx.x;
    if (i < NN) g_deg[i] = 0;
}

__global__ void k_hist(const void* __restrict__ ei) {
    int e = blockIdx.x * blockDim.x + threadIdx.x;
    if (e < EE) atomicAdd(&g_deg[load_edge(ei, (long long)EE + e)], 1);
}

// blocks of 512: per-block exclusive scan + block sums
__global__ void k_scan1() {
    __shared__ int sh[512];
    int tid = threadIdx.x;
    int i = blockIdx.x * 512 + tid;
    int v = (i < NN) ? g_deg[i] : 0;
    sh[tid] = v;
    __syncthreads();
    for (int off = 1; off < 512; off <<= 1) {
        int t = 0;
        if (tid >= off) t = sh[tid - off];
        __syncthreads();
        sh[tid] += t;
        __syncthreads();
    }
    if (i < NN) g_off[i] = sh[tid] - v;      // exclusive within block
    if (tid == 511) g_bsum[blockIdx.x] = sh[511];
}

__global__ void k_scan2(int nb) {
    __shared__ int sh[128];
    int tid = threadIdx.x;
    int v = (tid < nb) ? g_bsum[tid] : 0;
    sh[tid] = v;
    __syncthreads();
    for (int off = 1; off < 128; off <<= 1) {
        int t = 0;
        if (tid >= off) t = sh[tid - off];
        __syncthreads();
        sh[tid] += t;
        __syncthreads();
    }
    g_boff[tid] = sh[tid] - v;
}

__global__ void k_scan3() {
    int i = blockIdx.x * blockDim.x + threadIdx.x;
    if (i < NN) {
        int o = g_off[i] + g_boff[i >> 9];
        g_off[i] = o;
        g_cursor[i] = o;
    }
    if (i == 0) g_off[NN] = EE;
}

__global__ void k_scatter(const void* __restrict__ ei) {
    int e = blockIdx.x * blockDim.x + threadIdx.x;
    if (e < EE) {
        int dst = load_edge(ei, (long long)EE + e);
        int src = load_edge(ei, e);
        int pos = atomicAdd(&g_cursor[dst], 1);
        if (pos < EE) g_csrc[pos] = src;
    }
}

// ---------------- fused 4-way projection GEMM (x @ {Wq,Wk,Wv,Ws} + b) ------
// 128 threads, 32 rows/block. Thread (cp = tid&63, half = tid>>6) computes
// 16 rows x 2 cols with packed fma.rn.f32x2 (double-rate fp32 on sm_103a).
// x duplicated into both float2 halves in shared so one 8B load broadcasts.
// x_in == nullptr means "read from g_h". Outputs: g_q/g_k/g_v/g_skip.
__global__ void __launch_bounds__(128) k_proj(
    const float* __restrict__ x_in,
    const float* __restrict__ w0, const float* __restrict__ b0,
    const float* __restrict__ w1, const float* __restrict__ b1,
    const float* __restrict__ w2, const float* __restrict__ b2,
    const float* __restrict__ w3, const float* __restrict__ b3)
{
    __shared__ float2 xs[32][DD];

    const float* x = (x_in != nullptr) ? x_in : g_h;

    int tid = threadIdx.x;
    int row0 = blockIdx.x * 32;

    for (int i = tid; i < 32 * DD; i += 128) {
        int r = i >> 7, d = i & 127;
        int row = row0 + r;
        float v = (row < NN) ? x[row * DD + d] : 0.f;
        xs[r][d] = make_float2(v, v);
    }
    __syncthreads();

    int cp = tid & 63;              // cols 2cp, 2cp+1
    int rbase = (tid >> 6) * 16;    // rows rbase..rbase+15

    const float* Ws[4] = {w0, w1, w2, w3};
    const float* Bs[4] = {b0, b1, b2, b3};
    float* Os[4] = {g_q, g_k, g_v, g_skip};

    for (int m = 0; m < 4; m++) {
        const float* W = Ws[m];
        float2 bb = *(const float2*)(Bs[m] + 2 * cp);
        unsigned long long bpack = *reinterpret_cast<unsigned long long*>(&bb);
        unsigned long long acc[16];
#pragma unroll
        for (int r = 0; r < 16; r++) acc[r] = bpack;

#pragma unroll 8
        for (int d = 0; d < DD; d++) {
            float2 w2f = *(const float2*)(W + d * DD + 2 * cp);
            unsigned long long wp = *reinterpret_cast<unsigned long long*>(&w2f);
#pragma unroll
            for (int r = 0; r < 16; r++) {
                unsigned long long a =
                    *reinterpret_cast<const unsigned long long*>(&xs[rbase + r][d]);
                asm("fma.rn.f32x2 %0, %1, %2, %0;" : "+l"(acc[r]) : "l"(a), "l"(wp));
            }
        }

        float* O = Os[m];
#pragma unroll
        for (int r = 0; r < 16; r++) {
            int row = row0 + rbase + r;
            if (row < NN)
                *reinterpret_cast<float2*>(O + row * DD + 2 * cp) =
                    *reinterpret_cast<float2*>(&acc[r]);
        }
    }
}

// ---------------- warp-per-node online-softmax attention + skip ------------
// Lane l owns flat columns 4l..4l+3 (head = l>>3). Per edge: gather k4/v4
// (coalesced 512B each), per-head dot via 8-lane shfl reduce, online softmax
// rescale, accumulate v*e. No float atomics, no logit buffers.
// out_ptr == nullptr means "write to g_h and apply relu".
__global__ void __launch_bounds__(256) k_attn(float* out_ptr) {
    int node = (blockIdx.x * blockDim.x + threadIdx.x) >> 5;
    if (node >= NN) return;
    int lane = threadIdx.x & 31;

    int do_relu = (out_ptr == nullptr);
    float* out = do_relu ? g_h : out_ptr;

    const float4 q4 = *(const float4*)(g_q + node * DD + lane * 4);

    float4 acc = make_float4(0.f, 0.f, 0.f, 0.f);
    float m = -1e30f, s = 0.f;

    int start = g_off[node];
    int end = g_off[node + 1];

    for (int j = start; j < end; ++j) {
        int src = g_csrc[j];                                    // warp-broadcast
        const float4 k4 = *(const float4*)(g_k + src * DD + lane * 4);
        const float4 v4 = *(const float4*)(g_v + src * DD + lane * 4);

        float t = q4.x * k4.x + q4.y * k4.y + q4.z * k4.z + q4.w * k4.w;
        t += __shfl_xor_sync(0xffffffffu, t, 1);
        t += __shfl_xor_sync(0xffffffffu, t, 2);
        t += __shfl_xor_sync(0xffffffffu, t, 4);   // full per-head (8-lane) dot

        float logit = t * 0.17677669529663689f;    // 1/sqrt(32)
        float nm = fmaxf(m, logit);
        float fac = __expf(m - nm);
        float e = __expf(logit - nm);
        s = s * fac + e;
        acc.x = acc.x * fac + v4.x * e;
        acc.y = acc.y * fac + v4.y * e;
        acc.z = acc.z * fac + v4.z * e;
        acc.w = acc.w * fac + v4.w * e;
        m = nm;
    }

    float inv = 1.f / (s + 1e-16f);
    const float4 sk = *(const float4*)(g_skip + node * DD + lane * 4);
    float4 o;
    o.x = acc.x * inv + sk.x;
    o.y = acc.y * inv + sk.y;
    o.z = acc.z * inv + sk.z;
    o.w = acc.w * inv + sk.w;
    if (do_relu) {
        o.x = fmaxf(o.x, 0.f);
        o.y = fmaxf(o.y, 0.f);
        o.z = fmaxf(o.z, 0.f);
        o.w = fmaxf(o.w, 0.f);
    }
    *(float4*)(out + node * DD + lane * 4) = o;
}

// ---------------- launch ----------------------------------------------------
extern "C" void kernel_launch(void* const* d_in, const int* in_sizes, int n_in,
                              void* d_out, int out_size) {
    const float* x = (const float*)d_in[0];
    const void* ei = d_in[1];    // int32 or int64 — detected on device
    const float* L0[8];
    const float* L1[8];
    for (int i = 0; i < 8; i++) {
        L0[i] = (const float*)d_in[2 + i];
        L1[i] = (const float*)d_in[10 + i];
    }
    float* out = (float*)d_out;

    const int NB_SCAN1 = (NN + 511) / 512;       // 98

    // edge dtype detection + CSR by destination
    k_detect<<<1, 256>>>((const int*)ei);
    k_zero_deg<<<(NN + 255) / 256, 256>>>();
    k_hist<<<(EE + 255) / 256, 256>>>(ei);
    k_scan1<<<NB_SCAN1, 512>>>();
    k_scan2<<<1, 128>>>(NB_SCAN1);
    k_scan3<<<(NN + 255) / 256, 256>>>();
    k_scatter<<<(EE + 255) / 256, 256>>>(ei);

    const int PROJ_GRID = (NN + 31) / 32;        // 1563
    const int ATTN_GRID = (NN + 7) / 8;          // 6250

    // layer 0: read x, attn writes g_h with relu
    k_proj<<<PROJ_GRID, 128>>>(x,
        L0[0], L0[1], L0[2], L0[3], L0[4], L0[5], L0[6], L0[7]);
    k_attn<<<ATTN_GRID, 256>>>(nullptr);

    // layer 1: read g_h, attn writes d_out (no relu)
    k_proj<<<PROJ_GRID, 128>>>(nullptr,
        L1[0], L1[1], L1[2], L1[3], L1[4], L1[5], L1[6], L1[7]);
    k_attn<<<ATTN_GRID, 256>>>(out);
}